// round 2
// baseline (speedup 1.0000x reference)
#include <cuda_runtime.h>
#include <cuda_bf16.h>

#define NG 256
#define NN 128
#define NT 16
#define NM 10
#define NE 1024   // edges per graph

typedef unsigned long long f2;  // packed f32x2

__device__ __forceinline__ f2 pack2(float a, float b) {
    f2 r; asm("mov.b64 %0,{%1,%2};" : "=l"(r) : "f"(a), "f"(b)); return r;
}
__device__ __forceinline__ void unpack2(f2 x, float &a, float &b) {
    asm("mov.b64 {%0,%1},%2;" : "=f"(a), "=f"(b) : "l"(x));
}
__device__ __forceinline__ f2 fma2_(f2 a, f2 b, f2 c) {
    f2 r; asm("fma.rn.f32x2 %0,%1,%2,%3;" : "=l"(r) : "l"(a), "l"(b), "l"(c)); return r;
}
__device__ __forceinline__ f2 mul2_(f2 a, f2 b) {
    f2 r; asm("mul.rn.f32x2 %0,%1,%2;" : "=l"(r) : "l"(a), "l"(b)); return r;
}
__device__ __forceinline__ f2 add2_(f2 a, f2 b) {
    f2 r; asm("add.rn.f32x2 %0,%1,%2;" : "=l"(r) : "l"(a), "l"(b)); return r;
}
__device__ __forceinline__ float hadd2_(f2 x) { float a, b; unpack2(x, a, b); return a + b; }

// One warp per (graph b, template t). Block = 128 threads = 4 warps (4 templates).
// Grid = 1024 blocks: b = blockIdx.x>>2, t = (blockIdx.x&3)*4 + warp.
__global__ __launch_bounds__(128, 4)
void tgw_kernel(const int* __restrict__ ei,     // [2, NG*NE]
                const float* __restrict__ tadj, // [NT, NM, NM]
                const float* __restrict__ q0g,  // [NT, NM]
                float* __restrict__ out)        // [NG, NT]
{
    const int b    = blockIdx.x >> 2;
    const int w    = threadIdx.x >> 5;
    const int lane = threadIdx.x & 31;
    const int t    = ((blockIdx.x & 3) << 2) | w;

    __shared__ __align__(16) unsigned adjw[NN * 4];      // adjacency bitmask
    __shared__ float f1p[NN];                            // deg/128
    __shared__ __align__(16) float Gs[4][NN * 12];       // per-warp G rows (pad 12)
    __shared__ __align__(8)  float C2x2[4][NM * NM];     // 2*C2
    __shared__ __align__(8)  f2    c2p[4][NM * 5];       // (2C2[2jj][m], 2C2[2jj+1][m])
    __shared__ __align__(8)  float qsh[4][NM];
    __shared__ __align__(8)  float f2qsh[4][NM];
    __shared__ __align__(8)  float vsh[4][12];
    __shared__ float red[4][NM][33];                     // column-reduce scratch

    // ---------- adjacency bitmask ----------
    for (int i = threadIdx.x; i < NN * 4; i += 128) adjw[i] = 0u;
    __syncthreads();
    for (int e = threadIdx.x; e < NE; e += 128) {
        int ge = b * NE + e;
        int s = ei[ge] & (NN - 1);
        int d = ei[NG * NE + ge] & (NN - 1);
        atomicOr(&adjw[(s << 2) + (d >> 5)], 1u << (d & 31));
        atomicOr(&adjw[(d << 2) + (s >> 5)], 1u << (s & 31));
    }
    __syncthreads();
    {
        int i = threadIdx.x;
        int dg = __popc(adjw[i * 4 + 0]) + __popc(adjw[i * 4 + 1])
               + __popc(adjw[i * 4 + 2]) + __popc(adjw[i * 4 + 3]);
        f1p[i] = (float)dg * (1.0f / NN);
    }

    // ---------- per-template constants ----------
    const float* C2g = tadj + t * NM * NM;
    for (int idx = lane; idx < NM * NM; idx += 32) C2x2[w][idx] = 2.0f * C2g[idx];
    __syncwarp();
    if (lane < NM) {                       // q = softmax(q0[t])
        float mx = -3.4e38f;
        #pragma unroll
        for (int j = 0; j < NM; ++j) mx = fmaxf(mx, q0g[t * NM + j]);
        float se = 0.f;
        #pragma unroll
        for (int j = 0; j < NM; ++j) se += __expf(q0g[t * NM + j] - mx);
        qsh[w][lane] = __expf(q0g[t * NM + lane] - mx) / se;
    }
    __syncwarp();
    if (lane < NM) {                       // f2q[i] = sum_j C2[i,j]^2 q[j]
        float acc = 0.f;
        #pragma unroll
        for (int j = 0; j < NM; ++j) { float c = C2g[lane * NM + j]; acc += c * c * qsh[w][j]; }
        f2qsh[w][lane] = acc;
    }
    __syncwarp();
    for (int idx = lane; idx < NM * 5; idx += 32) {      // column-pair view of 2*C2
        int m = idx / 5, jj = idx % 5;
        c2p[w][idx] = pack2(C2x2[w][(2 * jj) * NM + m], C2x2[w][(2 * jj + 1) * NM + m]);
    }
    __syncthreads();

    // ---------- per-warp registers ----------
    float* Gw = Gs[w];
    const f2* c2pw = c2p[w];
    float fi[4];
    f2 fi2[4];
    #pragma unroll
    for (int r = 0; r < 4; ++r) { fi[r] = f1p[lane + 32 * r]; fi2[r] = pack2(fi[r], fi[r]); }
    f2 f2q2[5];
    #pragma unroll
    for (int mm = 0; mm < 5; ++mm) f2q2[mm] = *(const f2*)&f2qsh[w][2 * mm];
    const float qmine = qsh[w][lane < NM ? lane : 0];

    // ---------- K init: P0 = p q^T -> cross0[i,j] = f1p[i]*h0[j] ----------
    f2 K2[4][5];
    {
        f2 q2r[5];
        #pragma unroll
        for (int mm = 0; mm < 5; ++mm) q2r[mm] = *(const f2*)&qsh[w][2 * mm];
        float h0[NM];
        #pragma unroll
        for (int j = 0; j < NM; ++j) {
            const f2* cr = (const f2*)&C2x2[w][j * NM];
            f2 a = mul2_(q2r[0], cr[0]);
            #pragma unroll
            for (int mm = 1; mm < 5; ++mm) a = fma2_(q2r[mm], cr[mm], a);
            h0[j] = hadd2_(a);
        }
        #pragma unroll
        for (int r = 0; r < 4; ++r) {
            #pragma unroll
            for (int mm = 0; mm < 5; ++mm) {
                float t0 = fi[r] + f2qsh[w][2 * mm]     - fi[r] * h0[2 * mm];
                float t1 = fi[r] + f2qsh[w][2 * mm + 1] - fi[r] * h0[2 * mm + 1];
                K2[r][mm] = pack2(__expf(-20.f * t0), __expf(-20.f * t1));
            }
        }
    }

    const uint4* adjv = (const uint4*)adjw;
    const f2 NEG1 = 0xBF800000BF800000ULL;
    f2 v2[5];
    f2 uu2[4];
    float res = 0.f;

    #pragma unroll 1
    for (int outer = 0; outer < 5; ++outer) {
        #pragma unroll
        for (int mm = 0; mm < 5; ++mm) v2[mm] = 0x3F8000003F800000ULL;  // v = 1

        // ---------------- Sinkhorn: 20 iterations ----------------
        #pragma unroll 1
        for (int it = 0; it < 20; ++it) {
            // u = p / (K v)
            #pragma unroll
            for (int r = 0; r < 4; ++r) {
                f2 a = mul2_(K2[r][0], v2[0]);
                #pragma unroll
                for (int mm = 1; mm < 5; ++mm) a = fma2_(K2[r][mm], v2[mm], a);
                float u = __fdividef(1.0f / NN, hadd2_(a));
                uu2[r] = pack2(u, u);
            }
            // per-lane column partials: part[j] = sum_r K[r][j]*u[r]
            #pragma unroll
            for (int mm = 0; mm < 5; ++mm) {
                f2 a = mul2_(K2[0][mm], uu2[0]);
                #pragma unroll
                for (int r = 1; r < 4; ++r) a = fma2_(K2[r][mm], uu2[r], a);
                float pa, pb; unpack2(a, pa, pb);
                red[w][2 * mm][lane]     = pa;
                red[w][2 * mm + 1][lane] = pb;
            }
            __syncwarp();
            // column sums: lanes 0-9 rows [0,16), lanes 10-19 rows [16,32)
            {
                int j = lane % NM;
                int base0 = (lane >= NM) ? 16 : 0;
                const float* rj = &red[w][j][0];
                float a0 = rj[base0 + 0], a1 = rj[base0 + 1];
                float a2 = rj[base0 + 2], a3 = rj[base0 + 3];
                a0 += rj[base0 + 4];  a1 += rj[base0 + 5];
                a2 += rj[base0 + 6];  a3 += rj[base0 + 7];
                a0 += rj[base0 + 8];  a1 += rj[base0 + 9];
                a2 += rj[base0 + 10]; a3 += rj[base0 + 11];
                a0 += rj[base0 + 12]; a1 += rj[base0 + 13];
                a2 += rj[base0 + 14]; a3 += rj[base0 + 15];
                float sHalf = (a0 + a1) + (a2 + a3);
                float sOther = __shfl_down_sync(0xFFFFFFFFu, sHalf, 10);
                if (lane < NM) vsh[w][lane] = __fdividef(qmine, sHalf + sOther);
            }
            __syncwarp();
            #pragma unroll
            for (int mm = 0; mm < 5; ++mm) v2[mm] = *(const f2*)&vsh[w][2 * mm];
        }

        // ---------------- build G = P * (2C2)^T into shared ----------------
        #pragma unroll
        for (int r = 0; r < 4; ++r) {
            f2 w2[5];
            #pragma unroll
            for (int mm = 0; mm < 5; ++mm)
                w2[mm] = mul2_(mul2_(K2[r][mm], v2[mm]), uu2[r]);   // P row values
            f2 wb[10];
            #pragma unroll
            for (int mm = 0; mm < 5; ++mm) {
                float a, b2; unpack2(w2[mm], a, b2);
                wb[2 * mm]     = pack2(a, a);
                wb[2 * mm + 1] = pack2(b2, b2);
            }
            f2 Gp[5];
            #pragma unroll
            for (int jj = 0; jj < 5; ++jj) {
                f2 a = mul2_(wb[0], c2pw[jj]);
                #pragma unroll
                for (int m = 1; m < NM; ++m) a = fma2_(wb[m], c2pw[m * 5 + jj], a);
                Gp[jj] = a;
            }
            f2* grow = (f2*)&Gw[(lane + 32 * r) * 12];
            #pragma unroll
            for (int jj = 0; jj < 5; ++jj) grow[jj] = Gp[jj];
        }
        __syncwarp();

        // ---------------- gather cross = C1 * G; then K-rebuild or final eval ----------------
        #pragma unroll 1
        for (int r = 0; r < 4; ++r) {
            int i = lane + 32 * r;
            uint4 aw = adjv[i];
            unsigned wd0 = aw.x, wd1 = aw.y, wd2 = aw.z, wd3 = aw.w;
            f2 acc0 = 0, acc1 = 0, acc2 = 0, acc3 = 0, acc4 = 0;
            #pragma unroll 1
            for (int wi = 0; wi < 4; ++wi) {
                unsigned msk = (wi == 0) ? wd0 : (wi == 1) ? wd1 : (wi == 2) ? wd2 : wd3;
                while (msk) {
                    int k = (wi << 5) + __ffs(msk) - 1;
                    msk &= msk - 1;
                    const f2* gk = (const f2*)&Gw[k * 12];
                    acc0 = add2_(acc0, gk[0]);
                    acc1 = add2_(acc1, gk[1]);
                    acc2 = add2_(acc2, gk[2]);
                    acc3 = add2_(acc3, gk[3]);
                    acc4 = add2_(acc4, gk[4]);
                }
            }
            f2 accs[5] = {acc0, acc1, acc2, acc3, acc4};
            if (outer < 4) {
                // new K = exp(-20 * (f1p[i] + f2q[j] - cross[i,j]))
                #pragma unroll
                for (int mm = 0; mm < 5; ++mm) {
                    f2 base = add2_(fi2[r], f2q2[mm]);
                    f2 tens = fma2_(accs[mm], NEG1, base);
                    float t0, t1; unpack2(tens, t0, t1);
                    K2[r][mm] = pack2(__expf(-20.f * t0), __expf(-20.f * t1));
                }
            } else {
                // res += sum_j tens[i,j] * P[i,j]
                f2 racc = 0;
                #pragma unroll
                for (int mm = 0; mm < 5; ++mm) {
                    f2 base = add2_(fi2[r], f2q2[mm]);
                    f2 tens = fma2_(accs[mm], NEG1, base);
                    f2 pij  = mul2_(mul2_(K2[r][mm], v2[mm]), uu2[r]);
                    racc = fma2_(tens, pij, racc);
                }
                res += hadd2_(racc);
            }
        }
    }

    // warp-reduce result, lane 0 writes
    #pragma unroll
    for (int off = 16; off; off >>= 1) res += __shfl_xor_sync(0xFFFFFFFFu, res, off);
    if (lane == 0) out[b * NT + t] = res;
}

extern "C" void kernel_launch(void* const* d_in, const int* in_sizes, int n_in,
                              void* d_out, int out_size) {
    // Identify inputs by element count (robust to ordering):
    //   edge_index: 2*NG*NE = 524288 int32
    //   tplt_adjacencies: NT*NM*NM = 1600 f32
    //   q0: NT*NM = 160 f32
    const int* ei = nullptr;
    const float* tadj = nullptr;
    const float* q0 = nullptr;
    for (int i = 0; i < n_in; ++i) {
        if (in_sizes[i] == 2 * NG * NE) ei = (const int*)d_in[i];
        else if (in_sizes[i] == NT * NM * NM) tadj = (const float*)d_in[i];
        else if (in_sizes[i] == NT * NM) q0 = (const float*)d_in[i];
    }
    float* out = (float*)d_out;
    tgw_kernel<<<NG * 4, 128>>>(ei, tadj, q0, out);
}

// round 3
// speedup vs baseline: 1.1222x; 1.1222x over previous
#include <cuda_runtime.h>
#include <cuda_bf16.h>

#define NG 256
#define NN 128
#define NT 16
#define NM 10
#define NE 1024   // edges per graph

typedef unsigned long long f2;  // packed f32x2

__device__ __forceinline__ f2 pack2(float a, float b) {
    f2 r; asm("mov.b64 %0,{%1,%2};" : "=l"(r) : "f"(a), "f"(b)); return r;
}
__device__ __forceinline__ void unpack2(f2 x, float &a, float &b) {
    asm("mov.b64 {%0,%1},%2;" : "=f"(a), "=f"(b) : "l"(x));
}
__device__ __forceinline__ f2 fma2_(f2 a, f2 b, f2 c) {
    f2 r; asm("fma.rn.f32x2 %0,%1,%2,%3;" : "=l"(r) : "l"(a), "l"(b), "l"(c)); return r;
}
__device__ __forceinline__ f2 mul2_(f2 a, f2 b) {
    f2 r; asm("mul.rn.f32x2 %0,%1,%2;" : "=l"(r) : "l"(a), "l"(b)); return r;
}
__device__ __forceinline__ f2 add2_(f2 a, f2 b) {
    f2 r; asm("add.rn.f32x2 %0,%1,%2;" : "=l"(r) : "l"(a), "l"(b)); return r;
}
__device__ __forceinline__ float hadd2_(f2 x) { float a, b; unpack2(x, a, b); return a + b; }

// Predicated accumulate: if (bit) K[0..4] += g[0..4]  (single setp, 5 @p add.f32x2;
// written in asm because C++ `if` lowers to BSSY/BSYNC branches).
__device__ __forceinline__ void madd5(f2* K, const f2* g, unsigned bit) {
    asm volatile(
        "{\n\t"
        ".reg .pred p;\n\t"
        "setp.ne.u32 p, %10, 0;\n\t"
        "@p add.rn.f32x2 %0, %0, %5;\n\t"
        "@p add.rn.f32x2 %1, %1, %6;\n\t"
        "@p add.rn.f32x2 %2, %2, %7;\n\t"
        "@p add.rn.f32x2 %3, %3, %8;\n\t"
        "@p add.rn.f32x2 %4, %4, %9;\n\t"
        "}"
        : "+l"(K[0]), "+l"(K[1]), "+l"(K[2]), "+l"(K[3]), "+l"(K[4])
        : "l"(g[0]), "l"(g[1]), "l"(g[2]), "l"(g[3]), "l"(g[4]), "r"(bit));
}

// One warp per (graph b, template t). Block = 128 threads = 4 warps.
__global__ __launch_bounds__(128, 4)
void tgw_kernel(const int* __restrict__ ei,     // [2, NG*NE]
                const float* __restrict__ tadj, // [NT, NM, NM]
                const float* __restrict__ q0g,  // [NT, NM]
                float* __restrict__ out)        // [NG, NT]
{
    const int b    = blockIdx.x >> 2;
    const int w    = threadIdx.x >> 5;
    const int lane = threadIdx.x & 31;
    const int t    = ((blockIdx.x & 3) << 2) | w;

    __shared__ __align__(16) unsigned adjw[NN * 4];      // adjacency bitmask
    __shared__ float f1p[NN];                            // deg/128
    __shared__ __align__(16) float Gs[4][NN * 12];       // per-warp Ghat rows (stride 12)
    __shared__ __align__(8)  float C2x2[4][NM * NM];     // 2*C2
    __shared__ __align__(8)  f2    c2p[4][NM * 5];       // NEGATED column pairs of 2*C2
    __shared__ __align__(8)  float qsh[4][NM];
    __shared__ __align__(8)  float f2qsh[4][NM];
    __shared__ __align__(8)  float vsh[4][12];
    __shared__ float red[4][NM][33];                     // column-reduce scratch

    // ---------- adjacency bitmask ----------
    for (int i = threadIdx.x; i < NN * 4; i += 128) adjw[i] = 0u;
    __syncthreads();
    for (int e = threadIdx.x; e < NE; e += 128) {
        int ge = b * NE + e;
        int s = ei[ge] & (NN - 1);
        int d = ei[NG * NE + ge] & (NN - 1);
        atomicOr(&adjw[(s << 2) + (d >> 5)], 1u << (d & 31));
        atomicOr(&adjw[(d << 2) + (s >> 5)], 1u << (s & 31));
    }
    __syncthreads();
    {
        int i = threadIdx.x;
        int dg = __popc(adjw[i * 4 + 0]) + __popc(adjw[i * 4 + 1])
               + __popc(adjw[i * 4 + 2]) + __popc(adjw[i * 4 + 3]);
        f1p[i] = (float)dg * (1.0f / NN);
    }

    // ---------- per-template constants ----------
    const float* C2g = tadj + t * NM * NM;
    for (int idx = lane; idx < NM * NM; idx += 32) C2x2[w][idx] = 2.0f * C2g[idx];
    __syncwarp();
    if (lane < NM) {                       // q = softmax(q0[t])
        float mx = -3.4e38f;
        #pragma unroll
        for (int j = 0; j < NM; ++j) mx = fmaxf(mx, q0g[t * NM + j]);
        float se = 0.f;
        #pragma unroll
        for (int j = 0; j < NM; ++j) se += __expf(q0g[t * NM + j] - mx);
        qsh[w][lane] = __expf(q0g[t * NM + lane] - mx) / se;
    }
    __syncwarp();
    if (lane < NM) {                       // f2q[i] = sum_j C2[i,j]^2 q[j]
        float acc = 0.f;
        #pragma unroll
        for (int j = 0; j < NM; ++j) { float c = C2g[lane * NM + j]; acc += c * c * qsh[w][j]; }
        f2qsh[w][lane] = acc;
    }
    __syncwarp();
    for (int idx = lane; idx < NM * 5; idx += 32) {      // NEGATED column-pair view of 2*C2
        int m = idx / 5, jj = idx % 5;
        c2p[w][idx] = pack2(-C2x2[w][(2 * jj) * NM + m], -C2x2[w][(2 * jj + 1) * NM + m]);
    }
    __syncthreads();

    // ---------- per-warp registers ----------
    float* Gw = Gs[w];
    const f2* c2pw = c2p[w];
    float fi[4];
    f2 fi2[4];
    #pragma unroll
    for (int r = 0; r < 4; ++r) { fi[r] = f1p[lane + 32 * r]; fi2[r] = pack2(fi[r], fi[r]); }
    f2 f2q2[5];
    #pragma unroll
    for (int mm = 0; mm < 5; ++mm) f2q2[mm] = *(const f2*)&f2qsh[w][2 * mm];
    const float qmine = qsh[w][lane < NM ? lane : 0];

    // ---------- K init: P0 = p q^T -> cross0[i,j] = f1p[i]*h0[j] ----------
    f2 K2[4][5];
    {
        f2 q2r[5];
        #pragma unroll
        for (int mm = 0; mm < 5; ++mm) q2r[mm] = *(const f2*)&qsh[w][2 * mm];
        float h0[NM];
        #pragma unroll
        for (int j = 0; j < NM; ++j) {
            const f2* cr = (const f2*)&C2x2[w][j * NM];
            f2 a = mul2_(q2r[0], cr[0]);
            #pragma unroll
            for (int mm = 1; mm < 5; ++mm) a = fma2_(q2r[mm], cr[mm], a);
            h0[j] = hadd2_(a);
        }
        #pragma unroll
        for (int r = 0; r < 4; ++r) {
            #pragma unroll
            for (int mm = 0; mm < 5; ++mm) {
                float t0 = fi[r] + f2qsh[w][2 * mm]     - fi[r] * h0[2 * mm];
                float t1 = fi[r] + f2qsh[w][2 * mm + 1] - fi[r] * h0[2 * mm + 1];
                K2[r][mm] = pack2(__expf(-20.f * t0), __expf(-20.f * t1));
            }
        }
    }

    f2 v2[5];
    f2 uu2[4];
    float res = 0.f;

    #pragma unroll 1
    for (int outer = 0; outer < 5; ++outer) {
        #pragma unroll
        for (int mm = 0; mm < 5; ++mm) v2[mm] = 0x3F8000003F800000ULL;  // v = 1

        // ---------------- Sinkhorn: 20 iterations ----------------
        #pragma unroll 1
        for (int it = 0; it < 20; ++it) {
            // u = p / (K v)
            #pragma unroll
            for (int r = 0; r < 4; ++r) {
                f2 a = mul2_(K2[r][0], v2[0]);
                #pragma unroll
                for (int mm = 1; mm < 5; ++mm) a = fma2_(K2[r][mm], v2[mm], a);
                float u = __fdividef(1.0f / NN, hadd2_(a));
                uu2[r] = pack2(u, u);
            }
            // per-lane column partials: part[j] = sum_r K[r][j]*u[r]
            #pragma unroll
            for (int mm = 0; mm < 5; ++mm) {
                f2 a = mul2_(K2[0][mm], uu2[0]);
                #pragma unroll
                for (int r = 1; r < 4; ++r) a = fma2_(K2[r][mm], uu2[r], a);
                float pa, pb; unpack2(a, pa, pb);
                red[w][2 * mm][lane]     = pa;
                red[w][2 * mm + 1][lane] = pb;
            }
            __syncwarp();
            // column sums: lanes 0-9 rows [0,16), lanes 10-19 rows [16,32)
            {
                int j = lane % NM;
                int base0 = (lane >= NM) ? 16 : 0;
                const float* rj = &red[w][j][0];
                float a0 = rj[base0 + 0], a1 = rj[base0 + 1];
                float a2 = rj[base0 + 2], a3 = rj[base0 + 3];
                a0 += rj[base0 + 4];  a1 += rj[base0 + 5];
                a2 += rj[base0 + 6];  a3 += rj[base0 + 7];
                a0 += rj[base0 + 8];  a1 += rj[base0 + 9];
                a2 += rj[base0 + 10]; a3 += rj[base0 + 11];
                a0 += rj[base0 + 12]; a1 += rj[base0 + 13];
                a2 += rj[base0 + 14]; a3 += rj[base0 + 15];
                float sHalf = (a0 + a1) + (a2 + a3);
                float sOther = __shfl_down_sync(0xFFFFFFFFu, sHalf, 10);
                if (lane < NM) vsh[w][lane] = __fdividef(qmine, sHalf + sOther);
            }
            __syncwarp();
            #pragma unroll
            for (int mm = 0; mm < 5; ++mm) v2[mm] = *(const f2*)&vsh[w][2 * mm];
        }

        // ---------------- build Ghat = -(P * (2C2)^T) into shared ----------------
        #pragma unroll
        for (int r = 0; r < 4; ++r) {
            f2 w2[5];
            #pragma unroll
            for (int mm = 0; mm < 5; ++mm)
                w2[mm] = mul2_(mul2_(K2[r][mm], v2[mm]), uu2[r]);   // P row values
            f2 wb[10];
            #pragma unroll
            for (int mm = 0; mm < 5; ++mm) {
                float a, b2; unpack2(w2[mm], a, b2);
                wb[2 * mm]     = pack2(a, a);
                wb[2 * mm + 1] = pack2(b2, b2);
            }
            f2 Gp[5];
            #pragma unroll
            for (int jj = 0; jj < 5; ++jj) {
                f2 a = mul2_(wb[0], c2pw[jj]);                  // c2p is negated
                #pragma unroll
                for (int m = 1; m < NM; ++m) a = fma2_(wb[m], c2pw[m * 5 + jj], a);
                Gp[jj] = a;
            }
            f2* grow = (f2*)&Gw[(lane + 32 * r) * 12];
            #pragma unroll
            for (int jj = 0; jj < 5; ++jj) grow[jj] = Gp[jj];
        }
        __syncwarp();

        if (outer < 4) {
            // ------- dense broadcast accumulate: K2 := f1p+f2q - cross = tens -------
            #pragma unroll
            for (int r = 0; r < 4; ++r)
                #pragma unroll
                for (int mm = 0; mm < 5; ++mm)
                    K2[r][mm] = add2_(fi2[r], f2q2[mm]);

            #pragma unroll 1
            for (int wb = 0; wb < 4; ++wb) {
                unsigned cur0 = adjw[(lane       ) * 4 + wb];
                unsigned cur1 = adjw[(lane +  32 ) * 4 + wb];
                unsigned cur2 = adjw[(lane +  64 ) * 4 + wb];
                unsigned cur3 = adjw[(lane +  96 ) * 4 + wb];
                const float* gbase = Gw + (wb << 5) * 12;
                #pragma unroll 4
                for (int kk = 0; kk < 32; ++kk) {
                    const f2* gk = (const f2*)(gbase + kk * 12);
                    f2 g[5] = {gk[0], gk[1], gk[2], gk[3], gk[4]};  // broadcast loads
                    madd5(&K2[0][0], g, cur0 & 1u);
                    madd5(&K2[1][0], g, cur1 & 1u);
                    madd5(&K2[2][0], g, cur2 & 1u);
                    madd5(&K2[3][0], g, cur3 & 1u);
                    cur0 >>= 1; cur1 >>= 1; cur2 >>= 1; cur3 >>= 1;
                }
            }
            // K = exp(-20 * tens), in place
            #pragma unroll
            for (int r = 0; r < 4; ++r) {
                #pragma unroll
                for (int mm = 0; mm < 5; ++mm) {
                    float t0, t1; unpack2(K2[r][mm], t0, t1);
                    K2[r][mm] = pack2(__expf(-20.f * t0), __expf(-20.f * t1));
                }
            }
        } else {
            // ------- final eval: sparse gather of Ghat; res += sum tens*P -------
            const uint4* adjv = (const uint4*)adjw;
            #pragma unroll 1
            for (int r = 0; r < 4; ++r) {
                int i = lane + 32 * r;
                uint4 aw = adjv[i];
                f2 acc0 = 0, acc1 = 0, acc2 = 0, acc3 = 0, acc4 = 0;
                #pragma unroll 1
                for (int wi = 0; wi < 4; ++wi) {
                    unsigned msk = (wi == 0) ? aw.x : (wi == 1) ? aw.y : (wi == 2) ? aw.z : aw.w;
                    while (msk) {
                        int k = (wi << 5) + __ffs(msk) - 1;
                        msk &= msk - 1;
                        const f2* gk = (const f2*)&Gw[k * 12];
                        acc0 = add2_(acc0, gk[0]);
                        acc1 = add2_(acc1, gk[1]);
                        acc2 = add2_(acc2, gk[2]);
                        acc3 = add2_(acc3, gk[3]);
                        acc4 = add2_(acc4, gk[4]);
                    }
                }
                f2 accs[5] = {acc0, acc1, acc2, acc3, acc4};
                f2 racc = 0;
                #pragma unroll
                for (int mm = 0; mm < 5; ++mm) {
                    f2 base = add2_(fi2[r], f2q2[mm]);
                    f2 tens = add2_(accs[mm], base);            // acc = -cross
                    f2 pij  = mul2_(mul2_(K2[r][mm], v2[mm]), uu2[r]);
                    racc = fma2_(tens, pij, racc);
                }
                res += hadd2_(racc);
            }
        }
    }

    // warp-reduce result, lane 0 writes
    #pragma unroll
    for (int off = 16; off; off >>= 1) res += __shfl_xor_sync(0xFFFFFFFFu, res, off);
    if (lane == 0) out[b * NT + t] = res;
}

extern "C" void kernel_launch(void* const* d_in, const int* in_sizes, int n_in,
                              void* d_out, int out_size) {
    const int* ei = nullptr;
    const float* tadj = nullptr;
    const float* q0 = nullptr;
    for (int i = 0; i < n_in; ++i) {
        if (in_sizes[i] == 2 * NG * NE) ei = (const int*)d_in[i];
        else if (in_sizes[i] == NT * NM * NM) tadj = (const float*)d_in[i];
        else if (in_sizes[i] == NT * NM) q0 = (const float*)d_in[i];
    }
    float* out = (float*)d_out;
    tgw_kernel<<<NG * 4, 128>>>(ei, tadj, q0, out);
}

// round 8
// speedup vs baseline: 1.7076x; 1.5216x over previous
#include <cuda_runtime.h>
#include <cuda_bf16.h>
#include <cstdint>

#define NG 256
#define NN 128
#define NT 16
#define NM 10
#define NE 1024

typedef unsigned long long f2;

__device__ __forceinline__ f2 pack2(float a, float b) {
    f2 r; asm("mov.b64 %0,{%1,%2};" : "=l"(r) : "f"(a), "f"(b)); return r;
}
__device__ __forceinline__ void unpack2(f2 x, float &a, float &b) {
    asm("mov.b64 {%0,%1},%2;" : "=f"(a), "=f"(b) : "l"(x));
}
__device__ __forceinline__ f2 fma2_(f2 a, f2 b, f2 c) {
    f2 r; asm("fma.rn.f32x2 %0,%1,%2,%3;" : "=l"(r) : "l"(a), "l"(b), "l"(c)); return r;
}
__device__ __forceinline__ f2 mul2_(f2 a, f2 b) {
    f2 r; asm("mul.rn.f32x2 %0,%1,%2;" : "=l"(r) : "l"(a), "l"(b)); return r;
}
__device__ __forceinline__ f2 add2_(f2 a, f2 b) {
    f2 r; asm("add.rn.f32x2 %0,%1,%2;" : "=l"(r) : "l"(a), "l"(b)); return r;
}
__device__ __forceinline__ float hadd2_(f2 x) { float a, b; unpack2(x, a, b); return a + b; }

// m16n8k16 row.col bf16 -> f32 (sm_80+ HMMA)
__device__ __forceinline__ void hmma(float* d, unsigned a0, unsigned a1, unsigned a2,
                                     unsigned a3, unsigned b0, unsigned b1) {
    asm volatile("mma.sync.aligned.m16n8k16.row.col.f32.bf16.bf16.f32 "
        "{%0,%1,%2,%3}, {%4,%5,%6,%7}, {%8,%9}, {%0,%1,%2,%3};"
        : "+f"(d[0]), "+f"(d[1]), "+f"(d[2]), "+f"(d[3])
        : "r"(a0), "r"(a1), "r"(a2), "r"(a3), "r"(b0), "r"(b1));
}
__device__ __forceinline__ unsigned bfp(unsigned p) {   // 2 adjacency bits -> bf16x2 of 1.0
    return ((p & 1u) ? 0x3F80u : 0u) | ((p & 2u) ? 0x3F800000u : 0u);
}

// smem carve (bytes): wbuf 4x2304 f32 @0 | afrag 64x32 uint4 @36864 | adjw @69632
// f1p @71680 | C2x2 @72192 | c2p @73792 | qsh @75392 | f2q @75552 | vsh @75712
#define SMEM_BYTES 75904

__global__ __launch_bounds__(128)
void tgw_kernel(const int* __restrict__ ei, const float* __restrict__ tadj,
                const float* __restrict__ q0g, float* __restrict__ out)
{
    extern __shared__ __align__(16) unsigned char sraw[];
    float*    wbufA = (float*)sraw;
    uint4*    afrag = (uint4*)(sraw + 36864);
    unsigned* adjw  = (unsigned*)(sraw + 69632);
    float*    f1p   = (float*)(sraw + 71680);
    float*    C2x2A = (float*)(sraw + 72192);
    f2*       c2pA  = (f2*)(sraw + 73792);
    float*    qshA  = (float*)(sraw + 75392);
    float*    f2qA  = (float*)(sraw + 75552);
    float*    vshA  = (float*)(sraw + 75712);

    const int b    = blockIdx.x >> 2;
    const int w    = threadIdx.x >> 5;
    const int lane = threadIdx.x & 31;
    const int t    = ((blockIdx.x & 3) << 2) | w;
    const int lq   = lane >> 2;
    const int lr   = lane & 3;

    float* wbufw = wbufA + w * 2304;
    float* C2w   = C2x2A + w * 100;
    f2*    c2pw  = c2pA + w * 50;
    float* qshw  = qshA + w * NM;
    float* f2qw  = f2qA + w * NM;
    float* vshw  = vshA + w * 12;

    // ---- adjacency bitmask ----
    for (int i = threadIdx.x; i < NN * 4; i += 128) adjw[i] = 0u;
    __syncthreads();
    for (int e = threadIdx.x; e < NE; e += 128) {
        int ge = b * NE + e;
        int s = ei[ge] & (NN - 1);
        int d = ei[NG * NE + ge] & (NN - 1);
        atomicOr(&adjw[(s << 2) + (d >> 5)], 1u << (d & 31));
        atomicOr(&adjw[(d << 2) + (s >> 5)], 1u << (s & 31));
    }
    __syncthreads();
    {
        int i = threadIdx.x;
        int dg = __popc(adjw[i*4]) + __popc(adjw[i*4+1]) + __popc(adjw[i*4+2]) + __popc(adjw[i*4+3]);
        f1p[i] = (float)dg * (1.0f / NN);
    }

    // ---- A-fragment cache: C1 as m16n8k16 A frags, set s = mt*8+kt ----
    for (int s = w; s < 64; s += 4) {
        int mt = s >> 3, kt = s & 7;
        int i0 = 16 * mt + lq;
        int k0 = 16 * kt + 2 * lr;
        unsigned w0 = adjw[i0 * 4 + (k0 >> 5)] >> (k0 & 31);
        unsigned w1 = adjw[(i0 + 8) * 4 + (k0 >> 5)] >> (k0 & 31);
        afrag[s * 32 + lane] = make_uint4(bfp(w0 & 3u), bfp(w1 & 3u),
                                          bfp((w0 >> 8) & 3u), bfp((w1 >> 8) & 3u));
    }

    // ---- per-template constants ----
    const float* C2g = tadj + t * NM * NM;
    for (int idx = lane; idx < NM * NM; idx += 32) C2w[idx] = 2.0f * C2g[idx];
    __syncwarp();
    if (lane < NM) {
        float mx = -3.4e38f;
        #pragma unroll
        for (int j = 0; j < NM; ++j) mx = fmaxf(mx, q0g[t * NM + j]);
        float se = 0.f;
        #pragma unroll
        for (int j = 0; j < NM; ++j) se += __expf(q0g[t * NM + j] - mx);
        qshw[lane] = __expf(q0g[t * NM + lane] - mx) / se;
    }
    __syncwarp();
    if (lane < NM) {
        float acc = 0.f;
        #pragma unroll
        for (int j = 0; j < NM; ++j) { float c = C2g[lane * NM + j]; acc += c * c * qshw[j]; }
        f2qw[lane] = acc;
    }
    __syncwarp();
    for (int idx = lane; idx < NM * 5; idx += 32) {
        int m = idx / 5, jj = idx % 5;
        c2pw[idx] = pack2(C2w[(2 * jj) * NM + m], C2w[(2 * jj + 1) * NM + m]);
    }
    __syncthreads();

    // ---- per-warp registers ----
    float fi[4]; f2 fi2[4];
    #pragma unroll
    for (int r = 0; r < 4; ++r) { fi[r] = f1p[lane + 32 * r]; fi2[r] = pack2(fi[r], fi[r]); }
    f2 f2q2[5];
    #pragma unroll
    for (int mm = 0; mm < 5; ++mm) f2q2[mm] = *(const f2*)&f2qw[2 * mm];
    const float qmine = qshw[lane < NM ? lane : 0];

    // ---- K init from P0 = p q^T ----
    f2 K2[4][5];
    {
        f2 q2r[5];
        #pragma unroll
        for (int mm = 0; mm < 5; ++mm) q2r[mm] = *(const f2*)&qshw[2 * mm];
        float h0[NM];
        #pragma unroll
        for (int j = 0; j < NM; ++j) {
            const f2* cr = (const f2*)&C2w[j * NM];
            f2 a = mul2_(q2r[0], cr[0]);
            #pragma unroll
            for (int mm = 1; mm < 5; ++mm) a = fma2_(q2r[mm], cr[mm], a);
            h0[j] = hadd2_(a);
        }
        #pragma unroll
        for (int r = 0; r < 4; ++r)
            #pragma unroll
            for (int mm = 0; mm < 5; ++mm) {
                float t0 = fi[r] + f2qw[2*mm]   - fi[r] * h0[2*mm];
                float t1 = fi[r] + f2qw[2*mm+1] - fi[r] * h0[2*mm+1];
                K2[r][mm] = pack2(__expf(-20.f * t0), __expf(-20.f * t1));
            }
    }

    const f2 NEG1 = 0xBF800000BF800000ULL;
    f2 v2[5], uu2[4];
    float res = 0.f;
    float* redw = wbufw;

    #pragma unroll 1
    for (int outer = 0; outer < 5; ++outer) {
        #pragma unroll
        for (int mm = 0; mm < 5; ++mm) v2[mm] = 0x3F8000003F800000ULL;

        // ---- Sinkhorn x20 (warp-local) ----
        #pragma unroll 1
        for (int it = 0; it < 20; ++it) {
            #pragma unroll
            for (int r = 0; r < 4; ++r) {
                f2 a = mul2_(K2[r][0], v2[0]);
                #pragma unroll
                for (int mm = 1; mm < 5; ++mm) a = fma2_(K2[r][mm], v2[mm], a);
                float u = __fdividef(1.0f / NN, hadd2_(a));
                uu2[r] = pack2(u, u);
            }
            #pragma unroll
            for (int mm = 0; mm < 5; ++mm) {
                f2 a = mul2_(K2[0][mm], uu2[0]);
                #pragma unroll
                for (int r = 1; r < 4; ++r) a = fma2_(K2[r][mm], uu2[r], a);
                float pa, pb; unpack2(a, pa, pb);
                redw[(2*mm)*33 + lane]   = pa;
                redw[(2*mm+1)*33 + lane] = pb;
            }
            __syncwarp();
            {
                int j = lane % NM;
                int b0 = (lane >= NM) ? 16 : 0;
                const float* rj = &redw[j * 33];
                float a0 = rj[b0+0]+rj[b0+4]+rj[b0+8]+rj[b0+12];
                float a1 = rj[b0+1]+rj[b0+5]+rj[b0+9]+rj[b0+13];
                float a2 = rj[b0+2]+rj[b0+6]+rj[b0+10]+rj[b0+14];
                float a3 = rj[b0+3]+rj[b0+7]+rj[b0+11]+rj[b0+15];
                float sH = (a0 + a1) + (a2 + a3);
                float sO = __shfl_down_sync(0xFFFFFFFFu, sH, 10);
                if (lane < NM) vshw[lane] = __fdividef(qmine, sH + sO);
            }
            __syncwarp();
            #pragma unroll
            for (int mm = 0; mm < 5; ++mm) v2[mm] = *(const f2*)&vshw[2 * mm];
        }

        // ---- G = P*(2C2)^T ----
        #pragma unroll
        for (int r = 0; r < 4; ++r) {
            f2 w2[5]; f2 wb[10]; float gv[10];
            #pragma unroll
            for (int mm = 0; mm < 5; ++mm) {
                w2[mm] = mul2_(mul2_(K2[r][mm], v2[mm]), uu2[r]);
                float a, b2; unpack2(w2[mm], a, b2);
                wb[2*mm] = pack2(a, a); wb[2*mm+1] = pack2(b2, b2);
            }
            #pragma unroll
            for (int jj = 0; jj < 5; ++jj) {
                f2 a = mul2_(wb[0], c2pw[jj]);
                #pragma unroll
                for (int m = 1; m < NM; ++m) a = fma2_(wb[m], c2pw[m * 5 + jj], a);
                unpack2(a, gv[2*jj], gv[2*jj+1]);
            }
            int k = lane + 32 * r;
            if (outer < 4) {
                __nv_bfloat16* gh = (__nv_bfloat16*)wbufw;   // hi rows [j][136]; lo @+2176
                #pragma unroll
                for (int j = 0; j < NM; ++j) {
                    float g = gv[j];
                    __nv_bfloat16 h = __float2bfloat16(g);
                    __nv_bfloat16 l2 = __float2bfloat16(g - __bfloat162float(h));
                    gh[j * 136 + k] = h;
                    gh[2176 + j * 136 + k] = l2;
                }
            } else {
                f2* grow = (f2*)&wbufw[k * 14];
                #pragma unroll
                for (int jj = 0; jj < 5; ++jj) grow[jj] = pack2(gv[2*jj], gv[2*jj+1]);
                #pragma unroll
                for (int mm = 0; mm < 5; ++mm) K2[r][mm] = w2[mm];   // stash P
            }
        }
        __syncwarp();

        if (outer < 4) {
            // ---- HMMA: cross = C1 * (G_hi + G_lo) ----
            const unsigned* gw = (const unsigned*)wbufw;   // 68 words/row; lo @+1088
            float acc[8][2][4];
            #pragma unroll
            for (int mt = 0; mt < 8; ++mt)
                #pragma unroll
                for (int nt = 0; nt < 2; ++nt) {
                    acc[mt][nt][0]=0.f; acc[mt][nt][1]=0.f; acc[mt][nt][2]=0.f; acc[mt][nt][3]=0.f;
                }
            const unsigned base0 = lq * 68 + lr;           // B row j=lq
            const unsigned base1 = (lq + 8) * 68 + lr;     // B row j=lq+8
            #pragma unroll 1
            for (int kt = 0; kt < 8; ++kt) {
                int o = kt * 8;
                unsigned bh00 = gw[base0+o],      bh01 = gw[base0+o+4];
                unsigned bh10 = gw[base1+o],      bh11 = gw[base1+o+4];
                unsigned bl00 = gw[base0+o+1088], bl01 = gw[base0+o+1092];
                unsigned bl10 = gw[base1+o+1088], bl11 = gw[base1+o+1092];
                const uint4* af = afrag + kt * 32 + lane;
                #pragma unroll
                for (int mt = 0; mt < 8; ++mt) {
                    uint4 a = af[mt * 256];
                    hmma(acc[mt][0], a.x, a.y, a.z, a.w, bh00, bh01);
                    hmma(acc[mt][1], a.x, a.y, a.z, a.w, bh10, bh11);
                    hmma(acc[mt][0], a.x, a.y, a.z, a.w, bl00, bl01);
                    hmma(acc[mt][1], a.x, a.y, a.z, a.w, bl10, bl11);
                }
            }
            // ---- store cross [128][14] then rebuild K ----
            float* cf = wbufw;
            #pragma unroll
            for (int mt = 0; mt < 8; ++mt)
                #pragma unroll
                for (int nt = 0; nt < 2; ++nt)
                    if (!(nt == 1 && lr == 3)) {           // cols 14,15 = pad
                        int col = 8 * nt + 2 * lr;
                        int i0 = 16 * mt + lq;
                        *(float2*)&cf[i0*14 + col]     = make_float2(acc[mt][nt][0], acc[mt][nt][1]);
                        *(float2*)&cf[(i0+8)*14 + col] = make_float2(acc[mt][nt][2], acc[mt][nt][3]);
                    }
            __syncwarp();
            #pragma unroll
            for (int r = 0; r < 4; ++r) {
                const f2* cr = (const f2*)&cf[(lane + 32 * r) * 14];
                #pragma unroll
                for (int mm = 0; mm < 5; ++mm) {
                    f2 base = add2_(fi2[r], f2q2[mm]);
                    f2 tens = fma2_(cr[mm], NEG1, base);
                    float t0, t1; unpack2(tens, t0, t1);
                    K2[r][mm] = pack2(__expf(-20.f * t0), __expf(-20.f * t1));
                }
            }
            __syncwarp();
        } else {
            // ---- final: sparse gather of G rows (stride 14), res += tens.P ----
            const uint4* adjv = (const uint4*)adjw;
            #pragma unroll 1
            for (int r = 0; r < 4; ++r) {
                uint4 aw = adjv[lane + 32 * r];
                f2 a0=0, a1=0, a2=0, a3=0, a4=0;
                #pragma unroll 1
                for (int wi = 0; wi < 4; ++wi) {
                    unsigned msk = (wi==0)?aw.x:(wi==1)?aw.y:(wi==2)?aw.z:aw.w;
                    while (msk) {
                        int kk = (wi << 5) + __ffs(msk) - 1;
                        msk &= msk - 1;
                        const f2* gk = (const f2*)&wbufw[kk * 14];
                        a0=add2_(a0,gk[0]); a1=add2_(a1,gk[1]); a2=add2_(a2,gk[2]);
                        a3=add2_(a3,gk[3]); a4=add2_(a4,gk[4]);
                    }
                }
                f2 accs[5] = {a0,a1,a2,a3,a4};
                f2 racc = 0;
                #pragma unroll
                for (int mm = 0; mm < 5; ++mm) {
                    f2 base = add2_(fi2[r], f2q2[mm]);
                    f2 tens = fma2_(accs[mm], NEG1, base);
                    racc = fma2_(tens, K2[r][mm], racc);    // K2 holds P
                }
                res += hadd2_(racc);
            }
        }
    }

    #pragma unroll
    for (int off = 16; off; off >>= 1) res += __shfl_xor_sync(0xFFFFFFFFu, res, off);
    if (lane == 0) out[b * NT + t] = res;
}

extern "C" void kernel_launch(void* const* d_in, const int* in_sizes, int n_in,
                              void* d_out, int out_size) {
    const int* ei = nullptr; const float* tadj = nullptr; const float* q0 = nullptr;
    for (int i = 0; i < n_in; ++i) {
        if (in_sizes[i] == 2 * NG * NE) ei = (const int*)d_in[i];
        else if (in_sizes[i] == NT * NM * NM) tadj = (const float*)d_in[i];
        else if (in_sizes[i] == NT * NM) q0 = (const float*)d_in[i];
    }
    cudaFuncSetAttribute(tgw_kernel, cudaFuncAttributeMaxDynamicSharedMemorySize, SMEM_BYTES);
    tgw_kernel<<<NG * 4, 128, SMEM_BYTES>>>(ei, tadj, q0, (float*)d_out);
}